// round 2
// baseline (speedup 1.0000x reference)
#include <cuda_runtime.h>
#include <math.h>

// Problem constants
#define NT    16384      // B*T tokens
#define DIMQ  512
#define HEADS 8
#define DHEAD 64
#define TLEN  4096       // T per batch
#define NB    4          // batch

// Scratch (device globals — no allocation allowed)
__device__ float g_q[NT * DIMQ];
__device__ float g_k[NT * DIMQ];
__device__ float g_v[NT * DIMQ];
__device__ float g_att[NT * DIMQ];
__device__ float g_ctx[NB * HEADS * DHEAD * DHEAD];
__device__ float g_ctxp[NB * HEADS * 8 * DHEAD * DHEAD];
__device__ float g_ksump[NB * HEADS * 8 * DHEAD];

// ---------------------------------------------------------------------------
// SGEMM: C[m][n] = sum_k A[m][k] * W[n][k] + bias[n]
// M = NT, N = K = 512. Block tile 128x128, K-tile 16, 256 threads, 8x8 micro.
// ---------------------------------------------------------------------------
__global__ __launch_bounds__(256) void sgemm_bias_kernel(
    const float* __restrict__ A, const float* __restrict__ W,
    const float* __restrict__ bias, float* __restrict__ C)
{
    const int BM = 128, BN = 128, BK = 16;
    __shared__ float As[16][BM + 4];  // [k][m], padded
    __shared__ float Bs[16][BN + 4];  // [k][n], padded

    int tid = threadIdx.x;
    int m0 = blockIdx.y * BM;
    int n0 = blockIdx.x * BN;

    int w    = tid >> 5;
    int lane = tid & 31;
    int wm = w & 3;          // warp row 0..3  (32 rows each)
    int wn = w >> 2;         // warp col 0..1  (64 cols each)
    int lm = lane >> 3;      // 0..3
    int ln = lane & 7;       // 0..7
    int row_base = wm * 32 + lm * 8;
    int col_base = wn * 64 + ln * 8;

    int lrow = tid >> 2;        // 0..63
    int lk4  = (tid & 3) * 4;   // 0,4,8,12

    float acc[8][8];
#pragma unroll
    for (int i = 0; i < 8; i++)
#pragma unroll
        for (int j = 0; j < 8; j++) acc[i][j] = 0.0f;

    for (int kt = 0; kt < DIMQ; kt += BK) {
        __syncthreads();
#pragma unroll
        for (int p = 0; p < 2; p++) {
            int r = p * 64 + lrow;
            float4 av = *(const float4*)&A[(size_t)(m0 + r) * DIMQ + kt + lk4];
            As[lk4 + 0][r] = av.x; As[lk4 + 1][r] = av.y;
            As[lk4 + 2][r] = av.z; As[lk4 + 3][r] = av.w;
            float4 bv = *(const float4*)&W[(size_t)(n0 + r) * DIMQ + kt + lk4];
            Bs[lk4 + 0][r] = bv.x; Bs[lk4 + 1][r] = bv.y;
            Bs[lk4 + 2][r] = bv.z; Bs[lk4 + 3][r] = bv.w;
        }
        __syncthreads();
#pragma unroll
        for (int kk = 0; kk < BK; kk++) {
            float4 a0 = *(const float4*)&As[kk][row_base];
            float4 a1 = *(const float4*)&As[kk][row_base + 4];
            float4 b0 = *(const float4*)&Bs[kk][col_base];
            float4 b1 = *(const float4*)&Bs[kk][col_base + 4];
            float af[8] = {a0.x, a0.y, a0.z, a0.w, a1.x, a1.y, a1.z, a1.w};
            float bf[8] = {b0.x, b0.y, b0.z, b0.w, b1.x, b1.y, b1.z, b1.w};
#pragma unroll
            for (int i = 0; i < 8; i++)
#pragma unroll
                for (int j = 0; j < 8; j++)
                    acc[i][j] += af[i] * bf[j];
        }
    }

    // Epilogue: add bias, store
    float4 bias0 = *(const float4*)&bias[n0 + col_base];
    float4 bias1 = *(const float4*)&bias[n0 + col_base + 4];
    float bb[8] = {bias0.x, bias0.y, bias0.z, bias0.w,
                   bias1.x, bias1.y, bias1.z, bias1.w};
#pragma unroll
    for (int i = 0; i < 8; i++) {
        size_t m = (size_t)(m0 + row_base + i);
        float4 c0 = make_float4(acc[i][0] + bb[0], acc[i][1] + bb[1],
                                acc[i][2] + bb[2], acc[i][3] + bb[3]);
        float4 c1 = make_float4(acc[i][4] + bb[4], acc[i][5] + bb[5],
                                acc[i][6] + bb[6], acc[i][7] + bb[7]);
        *(float4*)&C[m * DIMQ + n0 + col_base]     = c0;
        *(float4*)&C[m * DIMQ + n0 + col_base + 4] = c1;
    }
}

// ---------------------------------------------------------------------------
// Row softmax over contiguous 64-wide rows (per token, per head). In-place.
// One warp per row, 2 elements per lane.
// ---------------------------------------------------------------------------
__global__ __launch_bounds__(256) void softmax64_kernel(float* __restrict__ g)
{
    int row  = blockIdx.x * 8 + (threadIdx.x >> 5);
    int lane = threadIdx.x & 31;
    size_t base = (size_t)row * 64 + lane * 2;
    float2 x = *(float2*)&g[base];
    float m = fmaxf(x.x, x.y);
#pragma unroll
    for (int o = 16; o; o >>= 1) m = fmaxf(m, __shfl_xor_sync(0xffffffffu, m, o));
    float e0 = expf(x.x - m);
    float e1 = expf(x.y - m);
    float s = e0 + e1;
#pragma unroll
    for (int o = 16; o; o >>= 1) s += __shfl_xor_sync(0xffffffffu, s, o);
    float inv = 1.0f / s;
    *(float2*)&g[base] = make_float2(e0 * inv, e1 * inv);
}

// ---------------------------------------------------------------------------
// ksum partials: ksump[bh][s][d] = sum over 512 tokens of k[t][h*64+d]
// grid (32, 8), 64 threads
// ---------------------------------------------------------------------------
__global__ void ksum_partial_kernel(const float* __restrict__ K,
                                    float* __restrict__ ksump)
{
    int bh = blockIdx.x;
    int s  = blockIdx.y;
    int b = bh >> 3, h = bh & 7;
    int d = threadIdx.x;
    size_t base = ((size_t)b * TLEN + s * 512) * DIMQ + h * DHEAD + d;
    float acc = 0.0f;
#pragma unroll 8
    for (int t = 0; t < 512; t++) acc += K[base + (size_t)t * DIMQ];
    ksump[((size_t)bh * 8 + s) * DHEAD + d] = acc;
}

// ---------------------------------------------------------------------------
// Context partials: ctxp[bh][s][d][e] = sum over 512 tokens of k[t][d]*v[t][e]
// grid (32, 8), 256 threads, 4x4 micro on a 64x64 output tile
// ---------------------------------------------------------------------------
__global__ __launch_bounds__(256) void ctx_partial_kernel(
    const float* __restrict__ K, const float* __restrict__ V,
    float* __restrict__ ctxp)
{
    int bh = blockIdx.x;
    int s  = blockIdx.y;
    int b = bh >> 3, h = bh & 7;
    const size_t base = ((size_t)b * TLEN + s * 512) * DIMQ + h * DHEAD;

    __shared__ float ks[32][68];
    __shared__ float vs[32][68];

    int tid = threadIdx.x;
    int ty = tid >> 4, tx = tid & 15;
    float acc[4][4];
#pragma unroll
    for (int i = 0; i < 4; i++)
#pragma unroll
        for (int j = 0; j < 4; j++) acc[i][j] = 0.0f;

    int r  = tid >> 3;        // 0..31
    int d4 = (tid & 7) * 4;   // 0..28

    for (int c = 0; c < 16; c++) {
        __syncthreads();
        size_t g = base + (size_t)(c * 32 + r) * DIMQ + d4;
        *(float4*)&ks[r][d4]      = *(const float4*)&K[g];
        *(float4*)&ks[r][d4 + 32] = *(const float4*)&K[g + 32];
        *(float4*)&vs[r][d4]      = *(const float4*)&V[g];
        *(float4*)&vs[r][d4 + 32] = *(const float4*)&V[g + 32];
        __syncthreads();
#pragma unroll
        for (int tt = 0; tt < 32; tt++) {
            float af[4], bf[4];
#pragma unroll
            for (int i = 0; i < 4; i++) af[i] = ks[tt][ty + 16 * i];
#pragma unroll
            for (int j = 0; j < 4; j++) bf[j] = vs[tt][tx + 16 * j];
#pragma unroll
            for (int i = 0; i < 4; i++)
#pragma unroll
                for (int j = 0; j < 4; j++) acc[i][j] += af[i] * bf[j];
        }
    }
    size_t obase = (size_t)(bh * 8 + s) * DHEAD * DHEAD;
#pragma unroll
    for (int i = 0; i < 4; i++)
#pragma unroll
        for (int j = 0; j < 4; j++)
            ctxp[obase + (size_t)(ty + 16 * i) * DHEAD + tx + 16 * j] = acc[i][j];
}

// ---------------------------------------------------------------------------
// Reduce context partials over the 8 T-splits. grid 32, 256 threads.
// ---------------------------------------------------------------------------
__global__ void ctx_reduce_kernel(const float* __restrict__ ctxp,
                                  float* __restrict__ ctx)
{
    int bh = blockIdx.x;
    for (int idx = threadIdx.x; idx < DHEAD * DHEAD; idx += blockDim.x) {
        float s = 0.0f;
#pragma unroll
        for (int p = 0; p < 8; p++)
            s += ctxp[(size_t)(bh * 8 + p) * DHEAD * DHEAD + idx];
        ctx[(size_t)bh * DHEAD * DHEAD + idx] = s;
    }
}

// ---------------------------------------------------------------------------
// Apply: att[t][h*64+e] = (sum_d q[t][d]*ctx[h][d][e]) * Dinv(t,h) + q[t][h*64+e]
// Dinv = 1 / sum_d q[t][d]*ksum[h][d]
// grid (8 heads, 256 token tiles of 64), 256 threads
// ---------------------------------------------------------------------------
__global__ __launch_bounds__(256) void attn_out_kernel(
    const float* __restrict__ Q, const float* __restrict__ ctx,
    const float* __restrict__ ksump, float* __restrict__ out)
{
    int h  = blockIdx.x;
    int t0 = blockIdx.y * 64;
    int b  = t0 / TLEN;
    int bh = b * HEADS + h;

    __shared__ float qst[64][68];   // [d][token]
    __shared__ float cs[64][68];    // [d][e]
    __shared__ float ksum[64];
    __shared__ float dinv[64];

    int tid = threadIdx.x;
    {
        int r  = tid >> 2;         // 0..63 token rows
        int d4 = (tid & 3) * 4;    // 0,4,8,12
#pragma unroll
        for (int p = 0; p < 4; p++) {
            int d = d4 + p * 16;
            float4 v = *(const float4*)&Q[(size_t)(t0 + r) * DIMQ + h * DHEAD + d];
            qst[d + 0][r] = v.x; qst[d + 1][r] = v.y;
            qst[d + 2][r] = v.z; qst[d + 3][r] = v.w;
        }
        int dr = tid >> 4;           // 0..15
        int e4 = (tid & 15) * 4;     // 0..60
#pragma unroll
        for (int p = 0; p < 4; p++) {
            int d = dr + p * 16;
            *(float4*)&cs[d][e4] =
                *(const float4*)&ctx[((size_t)bh * DHEAD + d) * DHEAD + e4];
        }
    }
    if (tid < 64) {
        float s = 0.0f;
#pragma unroll
        for (int p = 0; p < 8; p++)
            s += ksump[((size_t)bh * 8 + p) * DHEAD + tid];
        ksum[tid] = s;
    }
    __syncthreads();
    if (tid < 64) {
        float s = 0.0f;
#pragma unroll
        for (int d = 0; d < 64; d++) s += qst[d][tid] * ksum[d];
        dinv[tid] = 1.0f / s;
    }
    __syncthreads();

    int ty = tid >> 4, tx = tid & 15;
    float acc[4][4];
#pragma unroll
    for (int i = 0; i < 4; i++)
#pragma unroll
        for (int j = 0; j < 4; j++) acc[i][j] = 0.0f;

#pragma unroll 8
    for (int d = 0; d < 64; d++) {
        float af[4], bf[4];
#pragma unroll
        for (int i = 0; i < 4; i++) af[i] = qst[d][ty + 16 * i];
#pragma unroll
        for (int j = 0; j < 4; j++) bf[j] = cs[d][tx + 16 * j];
#pragma unroll
        for (int i = 0; i < 4; i++)
#pragma unroll
            for (int j = 0; j < 4; j++) acc[i][j] += af[i] * bf[j];
    }

#pragma unroll
    for (int i = 0; i < 4; i++) {
        int r = ty + 16 * i;
        float di = dinv[r];
#pragma unroll
        for (int j = 0; j < 4; j++) {
            int e = tx + 16 * j;
            out[(size_t)(t0 + r) * DIMQ + h * DHEAD + e] =
                acc[i][j] * di + qst[e][r];
        }
    }
}

// ---------------------------------------------------------------------------
extern "C" void kernel_launch(void* const* d_in, const int* in_sizes, int n_in,
                              void* d_out, int out_size)
{
    const float* x  = (const float*)d_in[0];
    const float* Wq = (const float*)d_in[1];
    const float* bq = (const float*)d_in[2];
    const float* Wk = (const float*)d_in[3];
    const float* bk = (const float*)d_in[4];
    const float* Wv = (const float*)d_in[5];
    const float* bv = (const float*)d_in[6];
    const float* Wp = (const float*)d_in[7];
    const float* bp = (const float*)d_in[8];
    float* out = (float*)d_out;

    float *q, *k, *v, *att, *ctx, *ctxp, *ksump;
    cudaGetSymbolAddress((void**)&q, g_q);
    cudaGetSymbolAddress((void**)&k, g_k);
    cudaGetSymbolAddress((void**)&v, g_v);
    cudaGetSymbolAddress((void**)&att, g_att);
    cudaGetSymbolAddress((void**)&ctx, g_ctx);
    cudaGetSymbolAddress((void**)&ctxp, g_ctxp);
    cudaGetSymbolAddress((void**)&ksump, g_ksump);

    dim3 gemm_grid(DIMQ / 128, NT / 128);  // (4, 128)

    sgemm_bias_kernel<<<gemm_grid, 256>>>(x, Wq, bq, q);
    sgemm_bias_kernel<<<gemm_grid, 256>>>(x, Wk, bk, k);
    sgemm_bias_kernel<<<gemm_grid, 256>>>(x, Wv, bv, v);

    softmax64_kernel<<<(NT * HEADS) / 8, 256>>>(q);
    softmax64_kernel<<<(NT * HEADS) / 8, 256>>>(k);

    ksum_partial_kernel<<<dim3(NB * HEADS, 8), 64>>>(k, ksump);
    ctx_partial_kernel<<<dim3(NB * HEADS, 8), 256>>>(k, v, ctxp);
    ctx_reduce_kernel<<<NB * HEADS, 256>>>(ctxp, ctx);

    attn_out_kernel<<<dim3(HEADS, NT / 64), 256>>>(q, ctx, ksump, att);

    sgemm_bias_kernel<<<gemm_grid, 256>>>(att, Wp, bp, out);
}

// round 4
// speedup vs baseline: 2.1151x; 2.1151x over previous
#include <cuda_runtime.h>
#include <cuda_bf16.h>
#include <cstdint>
#include <math.h>

// Problem constants
#define NT    16384      // B*T tokens
#define DIMQ  512
#define HEADS 8
#define DHEAD 64
#define TLEN  4096       // T per batch
#define NB    4          // batch

// ---------------------------------------------------------------------------
// Scratch (device globals — no allocation allowed)
// ---------------------------------------------------------------------------
__device__ float          g_q[NT * DIMQ];
__device__ float          g_k[NT * DIMQ];
__device__ float          g_v[NT * DIMQ];
__device__ __nv_bfloat16  g_xh[NT * DIMQ];
__device__ __nv_bfloat16  g_xl[NT * DIMQ];
__device__ __nv_bfloat16  g_atth[NT * DIMQ];
__device__ __nv_bfloat16  g_attl[NT * DIMQ];
__device__ __nv_bfloat16  g_wh[4 * DIMQ * DIMQ];
__device__ __nv_bfloat16  g_wl[4 * DIMQ * DIMQ];
__device__ float          g_ctx[NB * HEADS * DHEAD * DHEAD];
__device__ float          g_ctxp[NB * HEADS * 8 * DHEAD * DHEAD];
__device__ float          g_ksump[NB * HEADS * 8 * DHEAD];

#define SWZ128(x) ((x) ^ (((x) >> 3) & 0x70))

// ---------------------------------------------------------------------------
// warp-MMA helpers (portable sm_80+ path: LDSM + HMMA + LDGSTS)
// ---------------------------------------------------------------------------
__device__ __forceinline__ uint32_t smem_u32(const void* p) {
    uint32_t a;
    asm("{ .reg .u64 t; cvta.to.shared.u64 t, %1; cvt.u32.u64 %0, t; }"
        : "=r"(a) : "l"(p));
    return a;
}

__device__ __forceinline__ void cp_async16(uint32_t saddr, const void* gaddr) {
    asm volatile("cp.async.cg.shared.global [%0], [%1], 16;"
                 :: "r"(saddr), "l"(gaddr) : "memory");
}
#define CP_COMMIT() asm volatile("cp.async.commit_group;" ::: "memory")
#define CP_WAIT2()  asm volatile("cp.async.wait_group 2;" ::: "memory")

__device__ __forceinline__ void ldsm4(uint32_t* r, uint32_t addr) {
    asm volatile("ldmatrix.sync.aligned.m8n8.x4.shared.b16 {%0,%1,%2,%3}, [%4];"
                 : "=r"(r[0]), "=r"(r[1]), "=r"(r[2]), "=r"(r[3]) : "r"(addr));
}

__device__ __forceinline__ void mma_bf16(float* c, const uint32_t* a,
                                         const uint32_t* b) {
    asm volatile(
        "mma.sync.aligned.m16n8k16.row.col.f32.bf16.bf16.f32 "
        "{%0,%1,%2,%3}, {%4,%5,%6,%7}, {%8,%9}, {%0,%1,%2,%3};"
        : "+f"(c[0]), "+f"(c[1]), "+f"(c[2]), "+f"(c[3])
        : "r"(a[0]), "r"(a[1]), "r"(a[2]), "r"(a[3]), "r"(b[0]), "r"(b[1]));
}

// ---------------------------------------------------------------------------
// fp32 -> bf16 hi/lo split conversion (4 elems/thread)
// ---------------------------------------------------------------------------
__global__ __launch_bounds__(256) void hilo_kernel(
    const float* __restrict__ in, __nv_bfloat16* __restrict__ hi,
    __nv_bfloat16* __restrict__ lo)
{
    size_t i = ((size_t)blockIdx.x * 256 + threadIdx.x) * 4;
    float4 v = *(const float4*)(in + i);
    __nv_bfloat16 h0 = __float2bfloat16(v.x);
    __nv_bfloat16 h1 = __float2bfloat16(v.y);
    __nv_bfloat16 h2 = __float2bfloat16(v.z);
    __nv_bfloat16 h3 = __float2bfloat16(v.w);
    __nv_bfloat16 l0 = __float2bfloat16(v.x - __bfloat162float(h0));
    __nv_bfloat16 l1 = __float2bfloat16(v.y - __bfloat162float(h1));
    __nv_bfloat16 l2 = __float2bfloat16(v.z - __bfloat162float(h2));
    __nv_bfloat16 l3 = __float2bfloat16(v.w - __bfloat162float(h3));
    *(__nv_bfloat162*)(hi + i)     = __nv_bfloat162(h0, h1);
    *(__nv_bfloat162*)(hi + i + 2) = __nv_bfloat162(h2, h3);
    *(__nv_bfloat162*)(lo + i)     = __nv_bfloat162(l0, l1);
    *(__nv_bfloat162*)(lo + i + 2) = __nv_bfloat162(l2, l3);
}

// ---------------------------------------------------------------------------
// bf16x3 GEMM via warp MMA: C[m][n] = sum_k A[m][k]*W[n][k] + bias[n]
// BM=BN=128, BK=64; 8 warps (warp tile 32x64); 3-stage cp.async pipeline.
// grid (DIMQ/128=4, NT/128=128), 256 threads.
// ---------------------------------------------------------------------------
#define GBM 128
#define GBN 128
#define GKS 64
#define GNSL (DIMQ / GKS)            // 8 k-slices
#define TILE_BYTES (128 * 128)       // 16384 per tile (128 rows x 128B)
#define STAGE_BYTES (4 * TILE_BYTES) // Ah, Al, Wh, Wl
#define GEMM_SMEM (3 * STAGE_BYTES)  // 196608

__global__ __launch_bounds__(256) void gemm_bf16x3_kernel(
    const __nv_bfloat16* __restrict__ Ah, const __nv_bfloat16* __restrict__ Al,
    const __nv_bfloat16* __restrict__ Wh, const __nv_bfloat16* __restrict__ Wl,
    const float* __restrict__ bias, float* __restrict__ C)
{
    extern __shared__ __align__(1024) char sm[];
    uint32_t smb = smem_u32(sm);

    const int tid  = threadIdx.x;
    const int wid  = tid >> 5;
    const int lane = tid & 31;
    const int m0 = blockIdx.y * GBM;
    const int n0 = blockIdx.x * GBN;

    const int warp_m = wid & 3;   // 0..3 -> 32 rows each
    const int warp_n = wid >> 2;  // 0..1 -> 64 cols each
    const int mbase = warp_m * 32;
    const int nbase = warp_n * 64;

    const int lr = lane & 7;
    const int g  = lane >> 3;
    // ldmatrix per-thread local offsets (swizzle applied at use site)
    const uint32_t aoff = (uint32_t)(((g & 1) * 8 + lr) * 128 + (g >> 1) * 16);
    const uint32_t boff = (uint32_t)(((g >> 1) * 8 + lr) * 128 + (g & 1) * 16);

    const __nv_bfloat16* srcs[4] = {Ah, Al, Wh, Wl};

    float acc[2][8][4];
#pragma unroll
    for (int i = 0; i < 2; i++)
#pragma unroll
        for (int j = 0; j < 8; j++)
#pragma unroll
            for (int c = 0; c < 4; c++) acc[i][j][c] = 0.0f;

    // ---- stage loader: 4 tiles x 1024 16B-chunks, 16 chunks/thread ----
    auto load_stage = [&](int s) {
        uint32_t stb = smb + (uint32_t)(s % 3) * STAGE_BYTES;
        int k0 = s * GKS;
#pragma unroll
        for (int t = 0; t < 4; t++) {
            const __nv_bfloat16* src = srcs[t];
            int r0 = (t < 2) ? m0 : n0;
            uint32_t tb = stb + (uint32_t)t * TILE_BYTES;
#pragma unroll
            for (int j = 0; j < 4; j++) {
                int il  = tid + j * 256;
                int row = il >> 3;
                int ch  = il & 7;
                uint32_t sa = tb + SWZ128((uint32_t)(row * 128 + ch * 16));
                const void* ga = src + (size_t)(r0 + row) * DIMQ + k0 + ch * 8;
                cp_async16(sa, ga);
            }
        }
    };

    load_stage(0); CP_COMMIT();
    load_stage(1); CP_COMMIT();

    for (int s = 0; s < GNSL; s++) {
        if (s + 2 < GNSL) load_stage(s + 2);
        CP_COMMIT();
        CP_WAIT2();
        __syncthreads();

        uint32_t stb  = smb + (uint32_t)(s % 3) * STAGE_BYTES;
        uint32_t ah_b = stb;
        uint32_t wh_b = stb + 2 * TILE_BYTES;

#pragma unroll
        for (int ks = 0; ks < 4; ks++) {
            uint32_t ksb = (uint32_t)(ks * 32);
            uint32_t aH[2][4], aL[2][4], bH[4][4], bL[4][4];
#pragma unroll
            for (int am = 0; am < 2; am++) {
                uint32_t ad = ah_b + (uint32_t)((mbase + am * 16) * 128)
                            + SWZ128(aoff + ksb);
                ldsm4(aH[am], ad);
                ldsm4(aL[am], ad + TILE_BYTES);
            }
#pragma unroll
            for (int nq = 0; nq < 4; nq++) {
                uint32_t bd = wh_b + (uint32_t)((nbase + nq * 16) * 128)
                            + SWZ128(boff + ksb);
                ldsm4(bH[nq], bd);
                ldsm4(bL[nq], bd + TILE_BYTES);
            }
#pragma unroll
            for (int am = 0; am < 2; am++)
#pragma unroll
                for (int na = 0; na < 8; na++) {
                    const uint32_t* bh = &bH[na >> 1][(na & 1) * 2];
                    const uint32_t* bl = &bL[na >> 1][(na & 1) * 2];
                    mma_bf16(acc[am][na], aH[am], bh);  // Ah*Wh
                    mma_bf16(acc[am][na], aH[am], bl);  // Ah*Wl
                    mma_bf16(acc[am][na], aL[am], bh);  // Al*Wh
                }
        }
        __syncthreads();
    }

    // ---- epilogue: add bias, store fp32 ----
    const int row_in = lane >> 2;        // 0..7
    const int col_in = (lane & 3) * 2;   // 0,2,4,6
#pragma unroll
    for (int am = 0; am < 2; am++) {
        int r = m0 + mbase + am * 16 + row_in;
#pragma unroll
        for (int na = 0; na < 8; na++) {
            int c = n0 + nbase + na * 8 + col_in;
            float2 b = *(const float2*)&bias[c];
            float2 v0 = make_float2(acc[am][na][0] + b.x, acc[am][na][1] + b.y);
            float2 v1 = make_float2(acc[am][na][2] + b.x, acc[am][na][3] + b.y);
            *(float2*)&C[(size_t)r * DIMQ + c]       = v0;
            *(float2*)&C[(size_t)(r + 8) * DIMQ + c] = v1;
        }
    }
}

// ---------------------------------------------------------------------------
// Row softmax over contiguous 64-wide rows (per token, per head). In-place.
// ---------------------------------------------------------------------------
__global__ __launch_bounds__(256) void softmax64_kernel(float* __restrict__ g)
{
    int row  = blockIdx.x * 8 + (threadIdx.x >> 5);
    int lane = threadIdx.x & 31;
    size_t base = (size_t)row * 64 + lane * 2;
    float2 x = *(float2*)&g[base];
    float m = fmaxf(x.x, x.y);
#pragma unroll
    for (int o = 16; o; o >>= 1) m = fmaxf(m, __shfl_xor_sync(0xffffffffu, m, o));
    float e0 = expf(x.x - m);
    float e1 = expf(x.y - m);
    float s = e0 + e1;
#pragma unroll
    for (int o = 16; o; o >>= 1) s += __shfl_xor_sync(0xffffffffu, s, o);
    float inv = 1.0f / s;
    *(float2*)&g[base] = make_float2(e0 * inv, e1 * inv);
}

// ---------------------------------------------------------------------------
// ksum partials
// ---------------------------------------------------------------------------
__global__ void ksum_partial_kernel(const float* __restrict__ K,
                                    float* __restrict__ ksump)
{
    int bh = blockIdx.x;
    int s  = blockIdx.y;
    int b = bh >> 3, h = bh & 7;
    int d = threadIdx.x;
    size_t base = ((size_t)b * TLEN + s * 512) * DIMQ + h * DHEAD + d;
    float acc = 0.0f;
#pragma unroll 8
    for (int t = 0; t < 512; t++) acc += K[base + (size_t)t * DIMQ];
    ksump[((size_t)bh * 8 + s) * DHEAD + d] = acc;
}

// ---------------------------------------------------------------------------
// Context partials
// ---------------------------------------------------------------------------
__global__ __launch_bounds__(256) void ctx_partial_kernel(
    const float* __restrict__ K, const float* __restrict__ V,
    float* __restrict__ ctxp)
{
    int bh = blockIdx.x;
    int s  = blockIdx.y;
    int b = bh >> 3, h = bh & 7;
    const size_t base = ((size_t)b * TLEN + s * 512) * DIMQ + h * DHEAD;

    __shared__ float ks[32][68];
    __shared__ float vs[32][68];

    int tid = threadIdx.x;
    int ty = tid >> 4, tx = tid & 15;
    float acc[4][4];
#pragma unroll
    for (int i = 0; i < 4; i++)
#pragma unroll
        for (int j = 0; j < 4; j++) acc[i][j] = 0.0f;

    int r  = tid >> 3;
    int d4 = (tid & 7) * 4;

    for (int c = 0; c < 16; c++) {
        __syncthreads();
        size_t g = base + (size_t)(c * 32 + r) * DIMQ + d4;
        *(float4*)&ks[r][d4]      = *(const float4*)&K[g];
        *(float4*)&ks[r][d4 + 32] = *(const float4*)&K[g + 32];
        *(float4*)&vs[r][d4]      = *(const float4*)&V[g];
        *(float4*)&vs[r][d4 + 32] = *(const float4*)&V[g + 32];
        __syncthreads();
#pragma unroll
        for (int tt = 0; tt < 32; tt++) {
            float af[4], bf[4];
#pragma unroll
            for (int i = 0; i < 4; i++) af[i] = ks[tt][ty + 16 * i];
#pragma unroll
            for (int j = 0; j < 4; j++) bf[j] = vs[tt][tx + 16 * j];
#pragma unroll
            for (int i = 0; i < 4; i++)
#pragma unroll
                for (int j = 0; j < 4; j++) acc[i][j] += af[i] * bf[j];
        }
    }
    size_t obase = (size_t)(bh * 8 + s) * DHEAD * DHEAD;
#pragma unroll
    for (int i = 0; i < 4; i++)
#pragma unroll
        for (int j = 0; j < 4; j++)
            ctxp[obase + (size_t)(ty + 16 * i) * DHEAD + tx + 16 * j] = acc[i][j];
}

__global__ void ctx_reduce_kernel(const float* __restrict__ ctxp,
                                  float* __restrict__ ctx)
{
    int bh = blockIdx.x;
    for (int idx = threadIdx.x; idx < DHEAD * DHEAD; idx += blockDim.x) {
        float s = 0.0f;
#pragma unroll
        for (int p = 0; p < 8; p++)
            s += ctxp[(size_t)(bh * 8 + p) * DHEAD * DHEAD + idx];
        ctx[(size_t)bh * DHEAD * DHEAD + idx] = s;
    }
}

// ---------------------------------------------------------------------------
// Apply attention + write att directly as bf16 hi/lo for the final GEMM
// ---------------------------------------------------------------------------
__global__ __launch_bounds__(256) void attn_out_kernel(
    const float* __restrict__ Q, const float* __restrict__ ctx,
    const float* __restrict__ ksump,
    __nv_bfloat16* __restrict__ outh, __nv_bfloat16* __restrict__ outl)
{
    int h  = blockIdx.x;
    int t0 = blockIdx.y * 64;
    int b  = t0 / TLEN;
    int bh = b * HEADS + h;

    __shared__ float qst[64][68];   // [d][token]
    __shared__ float cs[64][68];    // [d][e]
    __shared__ float ksum[64];
    __shared__ float dinv[64];

    int tid = threadIdx.x;
    {
        int r  = tid >> 2;
        int d4 = (tid & 3) * 4;
#pragma unroll
        for (int p = 0; p < 4; p++) {
            int d = d4 + p * 16;
            float4 v = *(const float4*)&Q[(size_t)(t0 + r) * DIMQ + h * DHEAD + d];
            qst[d + 0][r] = v.x; qst[d + 1][r] = v.y;
            qst[d + 2][r] = v.z; qst[d + 3][r] = v.w;
        }
        int dr = tid >> 4;
        int e4 = (tid & 15) * 4;
#pragma unroll
        for (int p = 0; p < 4; p++) {
            int d = dr + p * 16;
            *(float4*)&cs[d][e4] =
                *(const float4*)&ctx[((size_t)bh * DHEAD + d) * DHEAD + e4];
        }
    }
    if (tid < 64) {
        float s = 0.0f;
#pragma unroll
        for (int p = 0; p < 8; p++)
            s += ksump[((size_t)bh * 8 + p) * DHEAD + tid];
        ksum[tid] = s;
    }
    __syncthreads();
    if (tid < 64) {
        float s = 0.0f;
#pragma unroll
        for (int d = 0; d < 64; d++) s += qst[d][tid] * ksum[d];
        dinv[tid] = 1.0f / s;
    }
    __syncthreads();

    int ty = tid >> 4, tx = tid & 15;
    float acc[4][4];
#pragma unroll
    for (int i = 0; i < 4; i++)
#pragma unroll
        for (int j = 0; j < 4; j++) acc[i][j] = 0.0f;

#pragma unroll 8
    for (int d = 0; d < 64; d++) {
        float af[4], bf[4];
#pragma unroll
        for (int i = 0; i < 4; i++) af[i] = qst[d][ty + 16 * i];
#pragma unroll
        for (int j = 0; j < 4; j++) bf[j] = cs[d][tx + 16 * j];
#pragma unroll
        for (int i = 0; i < 4; i++)
#pragma unroll
            for (int j = 0; j < 4; j++) acc[i][j] += af[i] * bf[j];
    }

#pragma unroll
    for (int i = 0; i < 4; i++) {
        int r = ty + 16 * i;
        float di = dinv[r];
#pragma unroll
        for (int j = 0; j < 4; j++) {
            int e = tx + 16 * j;
            float val = acc[i][j] * di + qst[e][r];
            size_t idx = (size_t)(t0 + r) * DIMQ + h * DHEAD + e;
            __nv_bfloat16 hi = __float2bfloat16(val);
            outh[idx] = hi;
            outl[idx] = __float2bfloat16(val - __bfloat162float(hi));
        }
    }
}

// ---------------------------------------------------------------------------
extern "C" void kernel_launch(void* const* d_in, const int* in_sizes, int n_in,
                              void* d_out, int out_size)
{
    const float* x  = (const float*)d_in[0];
    const float* Wq = (const float*)d_in[1];
    const float* bq = (const float*)d_in[2];
    const float* Wk = (const float*)d_in[3];
    const float* bk = (const float*)d_in[4];
    const float* Wv = (const float*)d_in[5];
    const float* bv = (const float*)d_in[6];
    const float* Wp = (const float*)d_in[7];
    const float* bp = (const float*)d_in[8];
    float* out = (float*)d_out;

    float *q, *k, *v, *ctx, *ctxp, *ksump;
    __nv_bfloat16 *xh, *xl, *atth, *attl, *wh, *wl;
    cudaGetSymbolAddress((void**)&q, g_q);
    cudaGetSymbolAddress((void**)&k, g_k);
    cudaGetSymbolAddress((void**)&v, g_v);
    cudaGetSymbolAddress((void**)&ctx, g_ctx);
    cudaGetSymbolAddress((void**)&ctxp, g_ctxp);
    cudaGetSymbolAddress((void**)&ksump, g_ksump);
    cudaGetSymbolAddress((void**)&xh, g_xh);
    cudaGetSymbolAddress((void**)&xl, g_xl);
    cudaGetSymbolAddress((void**)&atth, g_atth);
    cudaGetSymbolAddress((void**)&attl, g_attl);
    cudaGetSymbolAddress((void**)&wh, g_wh);
    cudaGetSymbolAddress((void**)&wl, g_wl);

    cudaFuncSetAttribute(gemm_bf16x3_kernel,
                         cudaFuncAttributeMaxDynamicSharedMemorySize, GEMM_SMEM);

    const int WN = DIMQ * DIMQ;  // 262144 per weight matrix

    // hi/lo conversions
    hilo_kernel<<<(NT * DIMQ) / (256 * 4), 256>>>(x, xh, xl);
    hilo_kernel<<<WN / (256 * 4), 256>>>(Wq, wh + 0 * WN, wl + 0 * WN);
    hilo_kernel<<<WN / (256 * 4), 256>>>(Wk, wh + 1 * WN, wl + 1 * WN);
    hilo_kernel<<<WN / (256 * 4), 256>>>(Wv, wh + 2 * WN, wl + 2 * WN);
    hilo_kernel<<<WN / (256 * 4), 256>>>(Wp, wh + 3 * WN, wl + 3 * WN);

    dim3 ggrid(DIMQ / GBN, NT / GBM);  // (4, 128)

    gemm_bf16x3_kernel<<<ggrid, 256, GEMM_SMEM>>>(xh, xl, wh + 0 * WN, wl + 0 * WN, bq, q);
    gemm_bf16x3_kernel<<<ggrid, 256, GEMM_SMEM>>>(xh, xl, wh + 1 * WN, wl + 1 * WN, bk, k);
    gemm_bf16x3_kernel<<<ggrid, 256, GEMM_SMEM>>>(xh, xl, wh + 2 * WN, wl + 2 * WN, bv, v);

    softmax64_kernel<<<(NT * HEADS) / 8, 256>>>(q);
    softmax64_kernel<<<(NT * HEADS) / 8, 256>>>(k);

    ksum_partial_kernel<<<dim3(NB * HEADS, 8), 64>>>(k, ksump);
    ctx_partial_kernel<<<dim3(NB * HEADS, 8), 256>>>(k, v, ctxp);
    ctx_reduce_kernel<<<NB * HEADS, 256>>>(ctxp, ctx);

    attn_out_kernel<<<dim3(HEADS, NT / 64), 256>>>(q, ctx, ksump, atth, attl);

    gemm_bf16x3_kernel<<<ggrid, 256, GEMM_SMEM>>>(atth, attl, wh + 3 * WN, wl + 3 * WN, bp, out);
}

// round 5
// speedup vs baseline: 2.1167x; 1.0008x over previous
#include <cuda_runtime.h>
#include <cuda_bf16.h>
#include <cstdint>
#include <math.h>

// Problem constants
#define NT    16384      // B*T tokens
#define DIMQ  512
#define HEADS 8
#define DHEAD 64
#define TLEN  4096       // T per batch
#define NB    4          // batch

// ---------------------------------------------------------------------------
// Scratch (device globals — no allocation allowed)
// ---------------------------------------------------------------------------
__device__ float          g_q[NT * DIMQ];
__device__ float          g_k[NT * DIMQ];
__device__ float          g_v[NT * DIMQ];
__device__ __nv_bfloat16  g_xh[NT * DIMQ];
__device__ __nv_bfloat16  g_xl[NT * DIMQ];
__device__ __nv_bfloat16  g_atth[NT * DIMQ];
__device__ __nv_bfloat16  g_attl[NT * DIMQ];
__device__ __nv_bfloat16  g_wh[4 * DIMQ * DIMQ];
__device__ __nv_bfloat16  g_wl[4 * DIMQ * DIMQ];
__device__ float          g_ctx[NB * HEADS * DHEAD * DHEAD];
__device__ float          g_ctxp[NB * HEADS * 8 * DHEAD * DHEAD];
__device__ float          g_ksump[NB * HEADS * 8 * DHEAD];

#define SWZ128(x) ((x) ^ (((x) >> 3) & 0x70))

// ---------------------------------------------------------------------------
// warp-MMA helpers (portable sm_80+ path: LDSM + HMMA + LDGSTS)
// ---------------------------------------------------------------------------
__device__ __forceinline__ uint32_t smem_u32(const void* p) {
    uint32_t a;
    asm("{ .reg .u64 t; cvta.to.shared.u64 t, %1; cvt.u32.u64 %0, t; }"
        : "=r"(a) : "l"(p));
    return a;
}

__device__ __forceinline__ void cp_async16(uint32_t saddr, const void* gaddr) {
    asm volatile("cp.async.cg.shared.global [%0], [%1], 16;"
                 :: "r"(saddr), "l"(gaddr) : "memory");
}
#define CP_COMMIT() asm volatile("cp.async.commit_group;" ::: "memory")
#define CP_WAIT2()  asm volatile("cp.async.wait_group 2;" ::: "memory")

__device__ __forceinline__ void ldsm4(uint32_t* r, uint32_t addr) {
    asm volatile("ldmatrix.sync.aligned.m8n8.x4.shared.b16 {%0,%1,%2,%3}, [%4];"
                 : "=r"(r[0]), "=r"(r[1]), "=r"(r[2]), "=r"(r[3]) : "r"(addr));
}

__device__ __forceinline__ void mma_bf16(float* c, const uint32_t* a,
                                         const uint32_t* b) {
    asm volatile(
        "mma.sync.aligned.m16n8k16.row.col.f32.bf16.bf16.f32 "
        "{%0,%1,%2,%3}, {%4,%5,%6,%7}, {%8,%9}, {%0,%1,%2,%3};"
        : "+f"(c[0]), "+f"(c[1]), "+f"(c[2]), "+f"(c[3])
        : "r"(a[0]), "r"(a[1]), "r"(a[2]), "r"(a[3]), "r"(b[0]), "r"(b[1]));
}

// ---------------------------------------------------------------------------
// fp32 -> bf16 hi/lo split conversion (4 elems/thread)
// ---------------------------------------------------------------------------
__global__ __launch_bounds__(256) void hilo_kernel(
    const float* __restrict__ in, __nv_bfloat16* __restrict__ hi,
    __nv_bfloat16* __restrict__ lo)
{
    size_t i = ((size_t)blockIdx.x * 256 + threadIdx.x) * 4;
    float4 v = *(const float4*)(in + i);
    __nv_bfloat16 h0 = __float2bfloat16(v.x);
    __nv_bfloat16 h1 = __float2bfloat16(v.y);
    __nv_bfloat16 h2 = __float2bfloat16(v.z);
    __nv_bfloat16 h3 = __float2bfloat16(v.w);
    __nv_bfloat16 l0 = __float2bfloat16(v.x - __bfloat162float(h0));
    __nv_bfloat16 l1 = __float2bfloat16(v.y - __bfloat162float(h1));
    __nv_bfloat16 l2 = __float2bfloat16(v.z - __bfloat162float(h2));
    __nv_bfloat16 l3 = __float2bfloat16(v.w - __bfloat162float(h3));
    *(__nv_bfloat162*)(hi + i)     = __nv_bfloat162(h0, h1);
    *(__nv_bfloat162*)(hi + i + 2) = __nv_bfloat162(h2, h3);
    *(__nv_bfloat162*)(lo + i)     = __nv_bfloat162(l0, l1);
    *(__nv_bfloat162*)(lo + i + 2) = __nv_bfloat162(l2, l3);
}

// ---------------------------------------------------------------------------
// bf16x3 GEMM via warp MMA: C[m][n] = sum_k A[m][k]*W[n][k] + bias[n]
// BM=BN=128, BK=64; 8 warps (warp tile 32x64); 3-stage cp.async pipeline.
// grid (DIMQ/128=4, NT/128=128), 256 threads.
// ---------------------------------------------------------------------------
#define GBM 128
#define GBN 128
#define GKS 64
#define GNSL (DIMQ / GKS)            // 8 k-slices
#define TILE_BYTES (128 * 128)       // 16384 per tile (128 rows x 128B)
#define STAGE_BYTES (4 * TILE_BYTES) // Ah, Al, Wh, Wl
#define GEMM_SMEM (3 * STAGE_BYTES)  // 196608

__global__ __launch_bounds__(256) void gemm_bf16x3_kernel(
    const __nv_bfloat16* __restrict__ Ah, const __nv_bfloat16* __restrict__ Al,
    const __nv_bfloat16* __restrict__ Wh, const __nv_bfloat16* __restrict__ Wl,
    const float* __restrict__ bias, float* __restrict__ C)
{
    extern __shared__ __align__(1024) char sm[];
    uint32_t smb = smem_u32(sm);

    const int tid  = threadIdx.x;
    const int wid  = tid >> 5;
    const int lane = tid & 31;
    const int m0 = blockIdx.y * GBM;
    const int n0 = blockIdx.x * GBN;

    const int warp_m = wid & 3;   // 0..3 -> 32 rows each
    const int warp_n = wid >> 2;  // 0..1 -> 64 cols each
    const int mbase = warp_m * 32;
    const int nbase = warp_n * 64;

    const int lr = lane & 7;
    const int g  = lane >> 3;
    // ldmatrix per-thread local offsets (swizzle applied at use site)
    const uint32_t aoff = (uint32_t)(((g & 1) * 8 + lr) * 128 + (g >> 1) * 16);
    const uint32_t boff = (uint32_t)(((g >> 1) * 8 + lr) * 128 + (g & 1) * 16);

    const __nv_bfloat16* srcs[4] = {Ah, Al, Wh, Wl};

    float acc[2][8][4];
#pragma unroll
    for (int i = 0; i < 2; i++)
#pragma unroll
        for (int j = 0; j < 8; j++)
#pragma unroll
            for (int c = 0; c < 4; c++) acc[i][j][c] = 0.0f;

    // ---- stage loader: 4 tiles x 1024 16B-chunks, 16 chunks/thread ----
    auto load_stage = [&](int s) {
        uint32_t stb = smb + (uint32_t)(s % 3) * STAGE_BYTES;
        int k0 = s * GKS;
#pragma unroll
        for (int t = 0; t < 4; t++) {
            const __nv_bfloat16* src = srcs[t];
            int r0 = (t < 2) ? m0 : n0;
            uint32_t tb = stb + (uint32_t)t * TILE_BYTES;
#pragma unroll
            for (int j = 0; j < 4; j++) {
                int il  = tid + j * 256;
                int row = il >> 3;
                int ch  = il & 7;
                uint32_t sa = tb + SWZ128((uint32_t)(row * 128 + ch * 16));
                const void* ga = src + (size_t)(r0 + row) * DIMQ + k0 + ch * 8;
                cp_async16(sa, ga);
            }
        }
    };

    load_stage(0); CP_COMMIT();
    load_stage(1); CP_COMMIT();

    for (int s = 0; s < GNSL; s++) {
        if (s + 2 < GNSL) load_stage(s + 2);
        CP_COMMIT();
        CP_WAIT2();
        __syncthreads();

        uint32_t stb  = smb + (uint32_t)(s % 3) * STAGE_BYTES;
        uint32_t ah_b = stb;
        uint32_t wh_b = stb + 2 * TILE_BYTES;

#pragma unroll
        for (int ks = 0; ks < 4; ks++) {
            uint32_t ksb = (uint32_t)(ks * 32);
            uint32_t aH[2][4], aL[2][4], bH[4][4], bL[4][4];
#pragma unroll
            for (int am = 0; am < 2; am++) {
                uint32_t ad = ah_b + (uint32_t)((mbase + am * 16) * 128)
                            + SWZ128(aoff + ksb);
                ldsm4(aH[am], ad);
                ldsm4(aL[am], ad + TILE_BYTES);
            }
#pragma unroll
            for (int nq = 0; nq < 4; nq++) {
                uint32_t bd = wh_b + (uint32_t)((nbase + nq * 16) * 128)
                            + SWZ128(boff + ksb);
                ldsm4(bH[nq], bd);
                ldsm4(bL[nq], bd + TILE_BYTES);
            }
#pragma unroll
            for (int am = 0; am < 2; am++)
#pragma unroll
                for (int na = 0; na < 8; na++) {
                    const uint32_t* bh = &bH[na >> 1][(na & 1) * 2];
                    const uint32_t* bl = &bL[na >> 1][(na & 1) * 2];
                    mma_bf16(acc[am][na], aH[am], bh);  // Ah*Wh
                    mma_bf16(acc[am][na], aH[am], bl);  // Ah*Wl
                    mma_bf16(acc[am][na], aL[am], bh);  // Al*Wh
                }
        }
        __syncthreads();
    }

    // ---- epilogue: add bias, store fp32 ----
    const int row_in = lane >> 2;        // 0..7
    const int col_in = (lane & 3) * 2;   // 0,2,4,6
#pragma unroll
    for (int am = 0; am < 2; am++) {
        int r = m0 + mbase + am * 16 + row_in;
#pragma unroll
        for (int na = 0; na < 8; na++) {
            int c = n0 + nbase + na * 8 + col_in;
            float2 b = *(const float2*)&bias[c];
            float2 v0 = make_float2(acc[am][na][0] + b.x, acc[am][na][1] + b.y);
            float2 v1 = make_float2(acc[am][na][2] + b.x, acc[am][na][3] + b.y);
            *(float2*)&C[(size_t)r * DIMQ + c]       = v0;
            *(float2*)&C[(size_t)(r + 8) * DIMQ + c] = v1;
        }
    }
}

// ---------------------------------------------------------------------------
// Row softmax over contiguous 64-wide rows (per token, per head). In-place.
// ---------------------------------------------------------------------------
__global__ __launch_bounds__(256) void softmax64_kernel(float* __restrict__ g)
{
    int row  = blockIdx.x * 8 + (threadIdx.x >> 5);
    int lane = threadIdx.x & 31;
    size_t base = (size_t)row * 64 + lane * 2;
    float2 x = *(float2*)&g[base];
    float m = fmaxf(x.x, x.y);
#pragma unroll
    for (int o = 16; o; o >>= 1) m = fmaxf(m, __shfl_xor_sync(0xffffffffu, m, o));
    float e0 = expf(x.x - m);
    float e1 = expf(x.y - m);
    float s = e0 + e1;
#pragma unroll
    for (int o = 16; o; o >>= 1) s += __shfl_xor_sync(0xffffffffu, s, o);
    float inv = 1.0f / s;
    *(float2*)&g[base] = make_float2(e0 * inv, e1 * inv);
}

// ---------------------------------------------------------------------------
// ksum partials
// ---------------------------------------------------------------------------
__global__ void ksum_partial_kernel(const float* __restrict__ K,
                                    float* __restrict__ ksump)
{
    int bh = blockIdx.x;
    int s  = blockIdx.y;
    int b = bh >> 3, h = bh & 7;
    int d = threadIdx.x;
    size_t base = ((size_t)b * TLEN + s * 512) * DIMQ + h * DHEAD + d;
    float acc = 0.0f;
#pragma unroll 8
    for (int t = 0; t < 512; t++) acc += K[base + (size_t)t * DIMQ];
    ksump[((size_t)bh * 8 + s) * DHEAD + d] = acc;
}

// ---------------------------------------------------------------------------
// Context partials
// ---------------------------------------------------------------------------
__global__ __launch_bounds__(256) void ctx_partial_kernel(
    const float* __restrict__ K, const float* __restrict__ V,
    float* __restrict__ ctxp)
{
    int bh = blockIdx.x;
    int s  = blockIdx.y;
    int b = bh >> 3, h = bh & 7;
    const size_t base = ((size_t)b * TLEN + s * 512) * DIMQ + h * DHEAD;

    __shared__ float ks[32][68];
    __shared__ float vs[32][68];

    int tid = threadIdx.x;
    int ty = tid >> 4, tx = tid & 15;
    float acc[4][4];
#pragma unroll
    for (int i = 0; i < 4; i++)
#pragma unroll
        for (int j = 0; j < 4; j++) acc[i][j] = 0.0f;

    int r  = tid >> 3;
    int d4 = (tid & 7) * 4;

    for (int c = 0; c < 16; c++) {
        __syncthreads();
        size_t g = base + (size_t)(c * 32 + r) * DIMQ + d4;
        *(float4*)&ks[r][d4]      = *(const float4*)&K[g];
        *(float4*)&ks[r][d4 + 32] = *(const float4*)&K[g + 32];
        *(float4*)&vs[r][d4]      = *(const float4*)&V[g];
        *(float4*)&vs[r][d4 + 32] = *(const float4*)&V[g + 32];
        __syncthreads();
#pragma unroll
        for (int tt = 0; tt < 32; tt++) {
            float af[4], bf[4];
#pragma unroll
            for (int i = 0; i < 4; i++) af[i] = ks[tt][ty + 16 * i];
#pragma unroll
            for (int j = 0; j < 4; j++) bf[j] = vs[tt][tx + 16 * j];
#pragma unroll
            for (int i = 0; i < 4; i++)
#pragma unroll
                for (int j = 0; j < 4; j++) acc[i][j] += af[i] * bf[j];
        }
    }
    size_t obase = (size_t)(bh * 8 + s) * DHEAD * DHEAD;
#pragma unroll
    for (int i = 0; i < 4; i++)
#pragma unroll
        for (int j = 0; j < 4; j++)
            ctxp[obase + (size_t)(ty + 16 * i) * DHEAD + tx + 16 * j] = acc[i][j];
}

__global__ void ctx_reduce_kernel(const float* __restrict__ ctxp,
                                  float* __restrict__ ctx)
{
    int bh = blockIdx.x;
    for (int idx = threadIdx.x; idx < DHEAD * DHEAD; idx += blockDim.x) {
        float s = 0.0f;
#pragma unroll
        for (int p = 0; p < 8; p++)
            s += ctxp[(size_t)(bh * 8 + p) * DHEAD * DHEAD + idx];
        ctx[(size_t)bh * DHEAD * DHEAD + idx] = s;
    }
}

// ---------------------------------------------------------------------------
// Apply attention + write att directly as bf16 hi/lo for the final GEMM
// ---------------------------------------------------------------------------
__global__ __launch_bounds__(256) void attn_out_kernel(
    const float* __restrict__ Q, const float* __restrict__ ctx,
    const float* __restrict__ ksump,
    __nv_bfloat16* __restrict__ outh, __nv_bfloat16* __restrict__ outl)
{
    int h  = blockIdx.x;
    int t0 = blockIdx.y * 64;
    int b  = t0 / TLEN;
    int bh = b * HEADS + h;

    __shared__ float qst[64][68];   // [d][token]
    __shared__ float cs[64][68];    // [d][e]
    __shared__ float ksum[64];
    __shared__ float dinv[64];

    int tid = threadIdx.x;
    {
        int r  = tid >> 2;
        int d4 = (tid & 3) * 4;
#pragma unroll
        for (int p = 0; p < 4; p++) {
            int d = d4 + p * 16;
            float4 v = *(const float4*)&Q[(size_t)(t0 + r) * DIMQ + h * DHEAD + d];
            qst[d + 0][r] = v.x; qst[d + 1][r] = v.y;
            qst[d + 2][r] = v.z; qst[d + 3][r] = v.w;
        }
        int dr = tid >> 4;
        int e4 = (tid & 15) * 4;
#pragma unroll
        for (int p = 0; p < 4; p++) {
            int d = dr + p * 16;
            *(float4*)&cs[d][e4] =
                *(const float4*)&ctx[((size_t)bh * DHEAD + d) * DHEAD + e4];
        }
    }
    if (tid < 64) {
        float s = 0.0f;
#pragma unroll
        for (int p = 0; p < 8; p++)
            s += ksump[((size_t)bh * 8 + p) * DHEAD + tid];
        ksum[tid] = s;
    }
    __syncthreads();
    if (tid < 64) {
        float s = 0.0f;
#pragma unroll
        for (int d = 0; d < 64; d++) s += qst[d][tid] * ksum[d];
        dinv[tid] = 1.0f / s;
    }
    __syncthreads();

    int ty = tid >> 4, tx = tid & 15;
    float acc[4][4];
#pragma unroll
    for (int i = 0; i < 4; i++)
#pragma unroll
        for (int j = 0; j < 4; j++) acc[i][j] = 0.0f;

#pragma unroll 8
    for (int d = 0; d < 64; d++) {
        float af[4], bf[4];
#pragma unroll
        for (int i = 0; i < 4; i++) af[i] = qst[d][ty + 16 * i];
#pragma unroll
        for (int j = 0; j < 4; j++) bf[j] = cs[d][tx + 16 * j];
#pragma unroll
        for (int i = 0; i < 4; i++)
#pragma unroll
            for (int j = 0; j < 4; j++) acc[i][j] += af[i] * bf[j];
    }

#pragma unroll
    for (int i = 0; i < 4; i++) {
        int r = ty + 16 * i;
        float di = dinv[r];
#pragma unroll
        for (int j = 0; j < 4; j++) {
            int e = tx + 16 * j;
            float val = acc[i][j] * di + qst[e][r];
            size_t idx = (size_t)(t0 + r) * DIMQ + h * DHEAD + e;
            __nv_bfloat16 hi = __float2bfloat16(val);
            outh[idx] = hi;
            outl[idx] = __float2bfloat16(val - __bfloat162float(hi));
        }
    }
}

// ---------------------------------------------------------------------------
extern "C" void kernel_launch(void* const* d_in, const int* in_sizes, int n_in,
                              void* d_out, int out_size)
{
    const float* x  = (const float*)d_in[0];
    const float* Wq = (const float*)d_in[1];
    const float* bq = (const float*)d_in[2];
    const float* Wk = (const float*)d_in[3];
    const float* bk = (const float*)d_in[4];
    const float* Wv = (const float*)d_in[5];
    const float* bv = (const float*)d_in[6];
    const float* Wp = (const float*)d_in[7];
    const float* bp = (const float*)d_in[8];
    float* out = (float*)d_out;

    float *q, *k, *v, *ctx, *ctxp, *ksump;
    __nv_bfloat16 *xh, *xl, *atth, *attl, *wh, *wl;
    cudaGetSymbolAddress((void**)&q, g_q);
    cudaGetSymbolAddress((void**)&k, g_k);
    cudaGetSymbolAddress((void**)&v, g_v);
    cudaGetSymbolAddress((void**)&ctx, g_ctx);
    cudaGetSymbolAddress((void**)&ctxp, g_ctxp);
    cudaGetSymbolAddress((void**)&ksump, g_ksump);
    cudaGetSymbolAddress((void**)&xh, g_xh);
    cudaGetSymbolAddress((void**)&xl, g_xl);
    cudaGetSymbolAddress((void**)&atth, g_atth);
    cudaGetSymbolAddress((void**)&attl, g_attl);
    cudaGetSymbolAddress((void**)&wh, g_wh);
    cudaGetSymbolAddress((void**)&wl, g_wl);

    cudaFuncSetAttribute(gemm_bf16x3_kernel,
                         cudaFuncAttributeMaxDynamicSharedMemorySize, GEMM_SMEM);

    const int WN = DIMQ * DIMQ;  // 262144 per weight matrix

    // hi/lo conversions
    hilo_kernel<<<(NT * DIMQ) / (256 * 4), 256>>>(x, xh, xl);
    hilo_kernel<<<WN / (256 * 4), 256>>>(Wq, wh + 0 * WN, wl + 0 * WN);
    hilo_kernel<<<WN / (256 * 4), 256>>>(Wk, wh + 1 * WN, wl + 1 * WN);
    hilo_kernel<<<WN / (256 * 4), 256>>>(Wv, wh + 2 * WN, wl + 2 * WN);
    hilo_kernel<<<WN / (256 * 4), 256>>>(Wp, wh + 3 * WN, wl + 3 * WN);

    dim3 ggrid(DIMQ / GBN, NT / GBM);  // (4, 128)

    gemm_bf16x3_kernel<<<ggrid, 256, GEMM_SMEM>>>(xh, xl, wh + 0 * WN, wl + 0 * WN, bq, q);
    gemm_bf16x3_kernel<<<ggrid, 256, GEMM_SMEM>>>(xh, xl, wh + 1 * WN, wl + 1 * WN, bk, k);
    gemm_bf16x3_kernel<<<ggrid, 256, GEMM_SMEM>>>(xh, xl, wh + 2 * WN, wl + 2 * WN, bv, v);

    softmax64_kernel<<<(NT * HEADS) / 8, 256>>>(q);
    softmax64_kernel<<<(NT * HEADS) / 8, 256>>>(k);

    ksum_partial_kernel<<<dim3(NB * HEADS, 8), 64>>>(k, ksump);
    ctx_partial_kernel<<<dim3(NB * HEADS, 8), 256>>>(k, v, ctxp);
    ctx_reduce_kernel<<<NB * HEADS, 256>>>(ctxp, ctx);

    attn_out_kernel<<<dim3(HEADS, NT / 64), 256>>>(q, ctx, ksump, atth, attl);

    gemm_bf16x3_kernel<<<ggrid, 256, GEMM_SMEM>>>(atth, attl, wh + 3 * WN, wl + 3 * WN, bp, out);
}